// round 8
// baseline (speedup 1.0000x reference)
#include <cuda_runtime.h>
#include <math.h>

// ---------------------------------------------------------------------------
// Problem constants
// ---------------------------------------------------------------------------
#define NB     4096
// conv1: 1 -> 32 ch, 28x28, pad 2, pool -> 14x14 (stored zero-padded 18x20)
// conv2: 32 -> 64 ch, 14x14, pad 2, pool -> 7x7
// fc1:   3136 -> 128, relu ; fc2: 128 -> 10

// Padded conv1-output: rows -2..15 (18), cols -2..17 (20, 16B-aligned rows)
#define P1R 18
#define P1C 20
#define P1A (P1R * P1C)          // 360

// ---------------------------------------------------------------------------
// cp.async helpers
// ---------------------------------------------------------------------------
__device__ __forceinline__ unsigned smem_u32(const void* p) {
    unsigned a;
    asm("{ .reg .u64 t; cvta.to.shared.u64 t, %1; cvt.u32.u64 %0, t; }"
        : "=r"(a) : "l"(p));
    return a;
}
__device__ __forceinline__ void cpa16(unsigned s, const void* g) {
    asm volatile("cp.async.cg.shared.global [%0], [%1], 16;" :: "r"(s), "l"(g));
}
#define CP_COMMIT() asm volatile("cp.async.commit_group;")
#define CP_WAIT1()  asm volatile("cp.async.wait_group 1;" ::: "memory")

// ---------------------------------------------------------------------------
// Device scratch
// ---------------------------------------------------------------------------
__device__ float g_K1[32 * 25];                  // [co][tap]
__device__ float g_K2[32 * 64 * 25];             // [ci][co][tap]
__device__ float g_pool1[NB * 32 * P1A];         // conv1 out, relu+pool, padded 18x20
__device__ float g_pool2[NB * 64 * 7 * 7];
__device__ float g_fc1o[NB * 128];
__device__ float g_fc1wt[3136 * 128];

// ---------------------------------------------------------------------------
// Kernel 1: build dense DCLS kernels
// ---------------------------------------------------------------------------
__global__ void build_kernels_k(const float* __restrict__ w1,
                                const float* __restrict__ p1,
                                const float* __restrict__ w2,
                                const float* __restrict__ p2) {
    int t = blockIdx.x * blockDim.x + threadIdx.x;
    if (t >= 32 + 64 * 32) return;

    float acc[36];
#pragma unroll
    for (int i = 0; i < 36; i++) acc[i] = 0.f;

    if (t < 32) {
        int co = t;
        for (int kc = 0; kc < 16; kc++) {
            float wv = w1[co * 16 + kc];
            float pa = p1[0 * 32 * 16 + co * 16 + kc];
            float pb = p1[1 * 32 * 16 + co * 16 + kc];
            pa = fminf(fmaxf(pa, -2.f), 2.f) + 2.f;
            pb = fminf(fmaxf(pb, -2.f), 2.f) + 2.f;
            int   i1 = (int)floorf(pa), i2 = (int)floorf(pb);
            float r1 = pa - (float)i1,  r2 = pb - (float)i2;
            acc[i1 * 6 + i2]           += wv * (1.f - r1) * (1.f - r2);
            acc[(i1 + 1) * 6 + i2]     += wv * r1 * (1.f - r2);
            acc[i1 * 6 + i2 + 1]       += wv * (1.f - r1) * r2;
            acc[(i1 + 1) * 6 + i2 + 1] += wv * r1 * r2;
        }
        for (int ky = 0; ky < 5; ky++)
            for (int kx = 0; kx < 5; kx++)
                g_K1[co * 25 + ky * 5 + kx] = acc[ky * 6 + kx];
    } else {
        int idx = t - 32;
        int co = idx / 32, ci = idx % 32;
        for (int kc = 0; kc < 32; kc++) {
            float wv = w2[(co * 32 + ci) * 32 + kc];
            float pa = p2[0 * 64 * 32 * 32 + (co * 32 + ci) * 32 + kc];
            float pb = p2[1 * 64 * 32 * 32 + (co * 32 + ci) * 32 + kc];
            pa = fminf(fmaxf(pa, -2.f), 2.f) + 2.f;
            pb = fminf(fmaxf(pb, -2.f), 2.f) + 2.f;
            int   i1 = (int)floorf(pa), i2 = (int)floorf(pb);
            float r1 = pa - (float)i1,  r2 = pb - (float)i2;
            acc[i1 * 6 + i2]           += wv * (1.f - r1) * (1.f - r2);
            acc[(i1 + 1) * 6 + i2]     += wv * r1 * (1.f - r2);
            acc[i1 * 6 + i2 + 1]       += wv * (1.f - r1) * r2;
            acc[(i1 + 1) * 6 + i2 + 1] += wv * r1 * r2;
        }
        // store as [ci][co][q] so conv2's smem chunk copy is a straight memcpy
        for (int ky = 0; ky < 5; ky++)
            for (int kx = 0; kx < 5; kx++)
                g_K2[(ci * 64 + co) * 25 + ky * 5 + kx] = acc[ky * 6 + kx];
    }
}

// ---------------------------------------------------------------------------
// Kernel 2: transpose fc1_w (128 x 3136) -> g_fc1wt (3136 x 128)
// ---------------------------------------------------------------------------
__global__ void transpose_fc1w_k(const float* __restrict__ w) {
    int idx = blockIdx.x * blockDim.x + threadIdx.x;
    if (idx < 3136 * 128) {
        int k = idx / 128, n = idx % 128;
        g_fc1wt[idx] = w[n * 3136 + k];
    }
}

// ---------------------------------------------------------------------------
// Kernel 3: conv1 (1->32, pad 2) + bias + relu + 2x2 maxpool, fused.
// Padded 32x32 image in smem; output in padded 18x20 layout.
// ---------------------------------------------------------------------------
__global__ __launch_bounds__(256) void conv1_k(const float* __restrict__ x,
                                               const float* __restrict__ b1) {
    __shared__ float xs[32 * 32];   // rows/cols -2..29
    __shared__ float ks[800];       // 32 x 25
    int b = blockIdx.x;
    const float* xp = x + b * 784;
    for (int i = threadIdx.x; i < 1024; i += 256) {
        int r = i / 32 - 2, c = i % 32 - 2;
        xs[i] = (r >= 0 && r < 28 && c >= 0 && c < 28) ? xp[r * 28 + c] : 0.f;
    }
    for (int i = threadIdx.x; i < 800; i += 256) ks[i] = g_K1[i];
    __syncthreads();

    float* outp = g_pool1 + b * 32 * P1A;
    for (int o = threadIdx.x; o < 32 * P1A; o += 256) {
        int co = o / P1A, m = o % P1A;
        int pr = m / P1C, pc = m % P1C;
        int yp = pr - 2,  xq = pc - 2;
        float outv = 0.f;
        if (yp >= 0 && yp < 14 && xq >= 0 && xq < 14) {
            int y0 = 2 * yp, x0 = 2 * xq;
            float patch[36];
#pragma unroll
            for (int dy = 0; dy < 6; dy++)
#pragma unroll
                for (int dx = 0; dx < 6; dx++)
                    patch[dy * 6 + dx] = xs[(y0 + dy) * 32 + (x0 + dx)];
            const float* kk = &ks[co * 25];
            float v0 = 0.f, v1 = 0.f, v2 = 0.f, v3 = 0.f;
#pragma unroll
            for (int ky = 0; ky < 5; ky++) {
#pragma unroll
                for (int kx = 0; kx < 5; kx++) {
                    float wv = kk[ky * 5 + kx];
                    v0 += wv * patch[(ky)     * 6 + kx];
                    v1 += wv * patch[(ky)     * 6 + kx + 1];
                    v2 += wv * patch[(ky + 1) * 6 + kx];
                    v3 += wv * patch[(ky + 1) * 6 + kx + 1];
                }
            }
            float mx = fmaxf(fmaxf(v0, v1), fmaxf(v2, v3)) + b1[co];
            outv = fmaxf(mx, 0.f);
        }
        outp[o] = outv;
    }
}

// ---------------------------------------------------------------------------
// Kernel 4: conv2 (32->64, pad 2) + bias + relu + pool.
// Scalar row-stationary math; input rows loaded as 5 x LDS.128 (16B-aligned
// 20-col rows) -> 55 LDS per ci instead of 133. cp.async double-buffered
// weight pipeline (8 chunks of 4 ci). smem 97.3 KB -> 2 CTAs/SM.
// ---------------------------------------------------------------------------
#define C2_THREADS 448
#define C2_IN_FLOATS (32 * P1A)                 // 11520 floats = 46080 B
#define C2_WCHUNK_CI 4
#define C2_W_FLOATS (C2_WCHUNK_CI * 64 * 25)    // 6400 floats = 25600 B
#define C2_NCHUNK 8
#define C2_SMEM_FLOATS (C2_IN_FLOATS + 2 * C2_W_FLOATS)   // 24320 floats

__global__ __launch_bounds__(C2_THREADS, 2) void conv2_k(const float* __restrict__ b2) {
    extern __shared__ float sm[];
    float* in_s = sm;                              // 32 x 360 padded input
    float* wbuf[2] = { sm + C2_IN_FLOATS,
                       sm + C2_IN_FLOATS + C2_W_FLOATS };

    int b = blockIdx.x;
    int t = threadIdx.x;

    unsigned in_sa = smem_u32(in_s);
    unsigned wba[2] = { smem_u32(wbuf[0]), smem_u32(wbuf[1]) };

    // group 0: input tile + weight chunk 0
    {
        const char* ip = (const char*)(g_pool1 + b * C2_IN_FLOATS);
        for (int i = t; i < C2_IN_FLOATS / 4; i += C2_THREADS)
            cpa16(in_sa + i * 16, ip + i * 16);
        const char* wp0 = (const char*)(g_K2);
        for (int i = t; i < C2_W_FLOATS / 4; i += C2_THREADS)
            cpa16(wba[0] + i * 16, wp0 + i * 16);
    }
    CP_COMMIT();
    // group 1: weight chunk 1
    {
        const char* wp1 = (const char*)(g_K2 + C2_W_FLOATS);
        for (int i = t; i < C2_W_FLOATS / 4; i += C2_THREADS)
            cpa16(wba[1] + i * 16, wp1 + i * 16);
    }
    CP_COMMIT();

    int yp = t / 64;     // 0..6
    int co = t % 64;     // 0..63
    int prow0 = 2 * yp;

    float acc0[14], acc1[14];
#pragma unroll
    for (int i = 0; i < 14; i++) { acc0[i] = 0.f; acc1[i] = 0.f; }

    for (int chunk = 0; chunk < C2_NCHUNK; chunk++) {
        CP_WAIT1();          // group for this chunk (and input) complete
        __syncthreads();

        const float* ws = wbuf[chunk & 1];
#pragma unroll 1
        for (int cil = 0; cil < C2_WCHUNK_CI; cil++) {
            int ci = chunk * C2_WCHUNK_CI + cil;
            const float* inc = in_s + ci * P1A;
            const float* wp  = ws + (cil * 64 + co) * 25;

#pragma unroll
            for (int j = 0; j < 6; j++) {
                // 16B-aligned row: 5 x LDS.128 covering cols 0..19
                const float4* rp = (const float4*)(inc + (prow0 + j) * P1C);
                float4 q0 = rp[0], q1 = rp[1], q2 = rp[2], q3 = rp[3], q4 = rp[4];
                float row[20];
                row[0]=q0.x;  row[1]=q0.y;  row[2]=q0.z;  row[3]=q0.w;
                row[4]=q1.x;  row[5]=q1.y;  row[6]=q1.z;  row[7]=q1.w;
                row[8]=q2.x;  row[9]=q2.y;  row[10]=q2.z; row[11]=q2.w;
                row[12]=q3.x; row[13]=q3.y; row[14]=q3.z; row[15]=q3.w;
                row[16]=q4.x; row[17]=q4.y; row[18]=q4.z; row[19]=q4.w;

                if (j < 5) {
#pragma unroll
                    for (int kx = 0; kx < 5; kx++) {
                        float wv = wp[j * 5 + kx];
#pragma unroll
                        for (int xx = 0; xx < 14; xx++)
                            acc0[xx] += wv * row[xx + kx];
                    }
                }
                if (j >= 1) {
#pragma unroll
                    for (int kx = 0; kx < 5; kx++) {
                        float wv = wp[(j - 1) * 5 + kx];
#pragma unroll
                        for (int xx = 0; xx < 14; xx++)
                            acc1[xx] += wv * row[xx + kx];
                    }
                }
            }
        }
        __syncthreads();     // all reads of wbuf[chunk&1] done

        // prefetch chunk+2 into the buffer just freed
        if (chunk + 2 < C2_NCHUNK) {
            const char* wn = (const char*)(g_K2 + (chunk + 2) * C2_W_FLOATS);
            unsigned dst = wba[chunk & 1];
            for (int i = t; i < C2_W_FLOATS / 4; i += C2_THREADS)
                cpa16(dst + i * 16, wn + i * 16);
        }
        CP_COMMIT();         // keep group accounting uniform
    }

    float bias = b2[co];
    float* op = g_pool2 + (b * 64 + co) * 49 + yp * 7;
#pragma unroll
    for (int xp = 0; xp < 7; xp++) {
        float m = fmaxf(fmaxf(acc0[2 * xp], acc0[2 * xp + 1]),
                        fmaxf(acc1[2 * xp], acc1[2 * xp + 1]));
        op[xp] = fmaxf(m + bias, 0.f);
    }
}

// ---------------------------------------------------------------------------
// Kernel 5: fc1 GEMM  C[4096,128] = pool2[4096,3136] @ Wt[3136,128] + b, relu
// ---------------------------------------------------------------------------
__global__ __launch_bounds__(256) void fc1_k(const float* __restrict__ fc1_b) {
    __shared__ float As[32 * 32];
    __shared__ float Bs[32 * 128];

    int m0 = blockIdx.x * 32;
    int tid = threadIdx.x;
    int tm = tid / 32;
    int tn = tid % 32;

    float c[4][4];
#pragma unroll
    for (int i = 0; i < 4; i++)
#pragma unroll
        for (int j = 0; j < 4; j++) c[i][j] = 0.f;

    const float* A = g_pool2;

    for (int k0 = 0; k0 < 3136; k0 += 32) {
#pragma unroll
        for (int l = 0; l < 4; l++) {
            int i = tid + l * 256;
            int mm = i / 32, kk = i % 32;
            As[mm * 32 + kk] = A[(m0 + mm) * 3136 + k0 + kk];
        }
#pragma unroll
        for (int l = 0; l < 16; l++) {
            int i = tid + l * 256;
            int kk = i / 128, n = i % 128;
            Bs[kk * 128 + n] = g_fc1wt[(k0 + kk) * 128 + n];
        }
        __syncthreads();

#pragma unroll
        for (int kk = 0; kk < 32; kk++) {
            float a0 = As[(tm * 4 + 0) * 32 + kk];
            float a1 = As[(tm * 4 + 1) * 32 + kk];
            float a2 = As[(tm * 4 + 2) * 32 + kk];
            float a3 = As[(tm * 4 + 3) * 32 + kk];
            float4 bv = *(const float4*)&Bs[kk * 128 + tn * 4];
            c[0][0] += a0 * bv.x; c[0][1] += a0 * bv.y; c[0][2] += a0 * bv.z; c[0][3] += a0 * bv.w;
            c[1][0] += a1 * bv.x; c[1][1] += a1 * bv.y; c[1][2] += a1 * bv.z; c[1][3] += a1 * bv.w;
            c[2][0] += a2 * bv.x; c[2][1] += a2 * bv.y; c[2][2] += a2 * bv.z; c[2][3] += a2 * bv.w;
            c[3][0] += a3 * bv.x; c[3][1] += a3 * bv.y; c[3][2] += a3 * bv.z; c[3][3] += a3 * bv.w;
        }
        __syncthreads();
    }

#pragma unroll
    for (int j = 0; j < 4; j++) {
        int m = m0 + tm * 4 + j;
#pragma unroll
        for (int jj = 0; jj < 4; jj++) {
            int n = tn * 4 + jj;
            g_fc1o[m * 128 + n] = fmaxf(c[j][jj] + fc1_b[n], 0.f);
        }
    }
}

// ---------------------------------------------------------------------------
// Kernel 6: fc2  out[4096,10] = fc1o[4096,128] @ fc2_w[10,128]^T + b
// ---------------------------------------------------------------------------
__global__ __launch_bounds__(256) void fc2_k(const float* __restrict__ fc2_w,
                                             const float* __restrict__ fc2_b,
                                             float* __restrict__ out) {
    int idx = blockIdx.x * blockDim.x + threadIdx.x;
    if (idx >= NB * 10) return;
    int m = idx / 10, n = idx % 10;
    const float4* h = (const float4*)(g_fc1o + m * 128);
    const float4* w = (const float4*)(fc2_w + n * 128);
    float s = 0.f;
#pragma unroll
    for (int i = 0; i < 32; i++) {
        float4 a = h[i], bb = w[i];
        s += a.x * bb.x + a.y * bb.y + a.z * bb.z + a.w * bb.w;
    }
    out[idx] = s + fc2_b[n];
}

// ---------------------------------------------------------------------------
// Launch
// ---------------------------------------------------------------------------
extern "C" void kernel_launch(void* const* d_in, const int* in_sizes, int n_in,
                              void* d_out, int out_size) {
    const float* x     = (const float*)d_in[0];
    const float* w1    = (const float*)d_in[1];
    const float* p1    = (const float*)d_in[2];
    const float* b1    = (const float*)d_in[3];
    const float* w2    = (const float*)d_in[4];
    const float* p2    = (const float*)d_in[5];
    const float* b2    = (const float*)d_in[6];
    const float* fc1w  = (const float*)d_in[7];
    const float* fc1b  = (const float*)d_in[8];
    const float* fc2w  = (const float*)d_in[9];
    const float* fc2b  = (const float*)d_in[10];
    float* out = (float*)d_out;

    cudaFuncSetAttribute(conv2_k, cudaFuncAttributeMaxDynamicSharedMemorySize,
                         C2_SMEM_FLOATS * 4);

    build_kernels_k<<<(32 + 64 * 32 + 127) / 128, 128>>>(w1, p1, w2, p2);
    transpose_fc1w_k<<<(3136 * 128 + 255) / 256, 256>>>(fc1w);
    conv1_k<<<NB, 256>>>(x, b1);
    conv2_k<<<NB, C2_THREADS, C2_SMEM_FLOATS * 4>>>(b2);
    fc1_k<<<NB / 32, 256>>>(fc1b);
    fc2_k<<<(NB * 10 + 255) / 256, 256>>>(fc2w, fc2b, out);
}

// round 9
// speedup vs baseline: 2.4051x; 2.4051x over previous
#include <cuda_runtime.h>
#include <math.h>

// ---------------------------------------------------------------------------
// Problem constants
// ---------------------------------------------------------------------------
#define NB     4096
// conv1: 1 -> 32 ch, 28x28, pad 2, pool -> 14x14
// conv2: 32 -> 64 ch, 14x14, pad 2, pool -> 7x7  (tensor-core implicit GEMM)
// fc1:   3136 -> 128, relu ; fc2: 128 -> 10

// conv1 output: padded spatial grid 18x18 (coords -2..15), channel-minor,
// position stride 36 floats (32 ci + 4 pad) -> conflict-free A fragments.
#define P1POS 324            // 18*18
#define P1POS_PAD 336        // padded so A-fragment reads of junk M rows stay in-bounds
#define P1STRIDE 36
#define P1FL (P1POS_PAD * P1STRIDE)   // 12096 floats per image

// ---------------------------------------------------------------------------
// helpers
// ---------------------------------------------------------------------------
__device__ __forceinline__ unsigned smem_u32(const void* p) {
    unsigned a;
    asm("{ .reg .u64 t; cvta.to.shared.u64 t, %1; cvt.u32.u64 %0, t; }"
        : "=r"(a) : "l"(p));
    return a;
}
__device__ __forceinline__ void cpa16(unsigned s, const void* g) {
    asm volatile("cp.async.cg.shared.global [%0], [%1], 16;" :: "r"(s), "l"(g));
}
#define CP_COMMIT() asm volatile("cp.async.commit_group;")
#define CP_WAIT1()  asm volatile("cp.async.wait_group 1;" ::: "memory")

__device__ __forceinline__ float to_tf32(float x) {
    unsigned r;
    asm("cvt.rna.tf32.f32 %0, %1;" : "=r"(r) : "f"(x));
    return __uint_as_float(r);
}

__device__ __forceinline__ void mma8(float c[4],
                                     unsigned a0, unsigned a1, unsigned a2, unsigned a3,
                                     unsigned b0, unsigned b1) {
    asm volatile("mma.sync.aligned.m16n8k8.row.col.f32.tf32.tf32.f32 "
                 "{%0,%1,%2,%3}, {%4,%5,%6,%7}, {%8,%9}, {%0,%1,%2,%3};"
                 : "+f"(c[0]), "+f"(c[1]), "+f"(c[2]), "+f"(c[3])
                 : "r"(a0), "r"(a1), "r"(a2), "r"(a3), "r"(b0), "r"(b1));
}

// ---------------------------------------------------------------------------
// Device scratch
// ---------------------------------------------------------------------------
__device__ float g_K1[32 * 25];                  // [co][tap]
__device__ float g_K2[32 * 64 * 25];             // dense [ci][co][tap]
__device__ float g_K2p[25 * 2048];               // packed tf32 B frags [tap][ks][nt][lane][2]
__device__ float g_pool1[NB * P1FL];             // conv1 out, tf32-rounded, [pos][ci]
__device__ float g_pool2[NB * 64 * 7 * 7];       // [b][pos*64+co]
__device__ float g_fc1o[NB * 128];
__device__ float g_fc1wt[3136 * 128];            // permuted to match g_pool2 layout

// ---------------------------------------------------------------------------
// Kernel 1: build dense DCLS kernels
// ---------------------------------------------------------------------------
__global__ void build_kernels_k(const float* __restrict__ w1,
                                const float* __restrict__ p1,
                                const float* __restrict__ w2,
                                const float* __restrict__ p2) {
    int t = blockIdx.x * blockDim.x + threadIdx.x;
    if (t >= 32 + 64 * 32) return;

    float acc[36];
#pragma unroll
    for (int i = 0; i < 36; i++) acc[i] = 0.f;

    if (t < 32) {
        int co = t;
        for (int kc = 0; kc < 16; kc++) {
            float wv = w1[co * 16 + kc];
            float pa = p1[0 * 32 * 16 + co * 16 + kc];
            float pb = p1[1 * 32 * 16 + co * 16 + kc];
            pa = fminf(fmaxf(pa, -2.f), 2.f) + 2.f;
            pb = fminf(fmaxf(pb, -2.f), 2.f) + 2.f;
            int   i1 = (int)floorf(pa), i2 = (int)floorf(pb);
            float r1 = pa - (float)i1,  r2 = pb - (float)i2;
            acc[i1 * 6 + i2]           += wv * (1.f - r1) * (1.f - r2);
            acc[(i1 + 1) * 6 + i2]     += wv * r1 * (1.f - r2);
            acc[i1 * 6 + i2 + 1]       += wv * (1.f - r1) * r2;
            acc[(i1 + 1) * 6 + i2 + 1] += wv * r1 * r2;
        }
        for (int ky = 0; ky < 5; ky++)
            for (int kx = 0; kx < 5; kx++)
                g_K1[co * 25 + ky * 5 + kx] = acc[ky * 6 + kx];
    } else {
        int idx = t - 32;
        int co = idx / 32, ci = idx % 32;
        for (int kc = 0; kc < 32; kc++) {
            float wv = w2[(co * 32 + ci) * 32 + kc];
            float pa = p2[0 * 64 * 32 * 32 + (co * 32 + ci) * 32 + kc];
            float pb = p2[1 * 64 * 32 * 32 + (co * 32 + ci) * 32 + kc];
            pa = fminf(fmaxf(pa, -2.f), 2.f) + 2.f;
            pb = fminf(fmaxf(pb, -2.f), 2.f) + 2.f;
            int   i1 = (int)floorf(pa), i2 = (int)floorf(pb);
            float r1 = pa - (float)i1,  r2 = pb - (float)i2;
            acc[i1 * 6 + i2]           += wv * (1.f - r1) * (1.f - r2);
            acc[(i1 + 1) * 6 + i2]     += wv * r1 * (1.f - r2);
            acc[i1 * 6 + i2 + 1]       += wv * (1.f - r1) * r2;
            acc[(i1 + 1) * 6 + i2 + 1] += wv * r1 * r2;
        }
        for (int ky = 0; ky < 5; ky++)
            for (int kx = 0; kx < 5; kx++)
                g_K2[(ci * 64 + co) * 25 + ky * 5 + kx] = acc[ky * 6 + kx];
    }
}

// ---------------------------------------------------------------------------
// Kernel 1b: repack conv2 weights into per-fragment tf32 layout.
// packed idx = ((tap*4 + ks)*8 + nt)*64 + lane*2 + h
//   maps to B[k][n] with k = ks*8 + (lane&3) + 4h, n = nt*8 + (lane>>2)
// ---------------------------------------------------------------------------
__global__ void repack_w2_k() {
    int idx = blockIdx.x * 256 + threadIdx.x;
    if (idx >= 25 * 2048) return;
    int tap = idx / 2048, r = idx % 2048;
    int ks = r >> 9;
    int r2 = r & 511;
    int nt = r2 >> 6;
    int r3 = r2 & 63;
    int lane = r3 >> 1, h = r3 & 1;
    int k = ks * 8 + (lane & 3) + 4 * h;
    int n = nt * 8 + (lane >> 2);
    g_K2p[idx] = to_tf32(g_K2[(k * 64 + n) * 25 + tap]);
}

// ---------------------------------------------------------------------------
// Kernel 2: transpose+permute fc1_w to match g_pool2 [pos*64+co] k-order.
// ---------------------------------------------------------------------------
__global__ void transpose_fc1w_k(const float* __restrict__ w) {
    int idx = blockIdx.x * blockDim.x + threadIdx.x;
    if (idx < 3136 * 128) {
        int kp = idx / 128, n = idx % 128;
        int pos = kp >> 6, co = kp & 63;
        g_fc1wt[idx] = w[n * 3136 + co * 49 + pos];
    }
}

// ---------------------------------------------------------------------------
// Kernel 3: conv1 (1->32, pad 2) + bias + relu + 2x2 maxpool.
// Output: channel-minor padded layout [pos(0..335)][ci], tf32-rounded.
// Warp processes one position for all 32 ci -> broadcast patch loads,
// coalesced 128B stores.
// ---------------------------------------------------------------------------
__global__ __launch_bounds__(256) void conv1_k(const float* __restrict__ x,
                                               const float* __restrict__ b1) {
    __shared__ float xs[32 * 32];   // rows/cols -2..29
    __shared__ float ks[800];       // 32 x 25
    int b = blockIdx.x;
    int tid = threadIdx.x;
    const float* xp = x + b * 784;
    for (int i = tid; i < 1024; i += 256) {
        int r = i / 32 - 2, c = i % 32 - 2;
        xs[i] = (r >= 0 && r < 28 && c >= 0 && c < 28) ? xp[r * 28 + c] : 0.f;
    }
    for (int i = tid; i < 800; i += 256) ks[i] = g_K1[i];
    __syncthreads();

    float* outp = g_pool1 + b * P1FL;
    // zero the tail pad rows (pos 324..335, ci 0..31)
    if (tid < 384) {
        int p = P1POS + (tid >> 5);
        outp[p * P1STRIDE + (tid & 31)] = 0.f;
    }

    for (int o = tid; o < P1POS * 32; o += 256) {
        int pos = o >> 5, ci = o & 31;
        int pr = pos / 18, pc = pos % 18;
        int yp = pr - 2,  xq = pc - 2;
        float outv = 0.f;
        if (yp >= 0 && yp < 14 && xq >= 0 && xq < 14) {
            int y0 = 2 * yp, x0 = 2 * xq;
            float patch[36];
#pragma unroll
            for (int dy = 0; dy < 6; dy++)
#pragma unroll
                for (int dx = 0; dx < 6; dx++)
                    patch[dy * 6 + dx] = xs[(y0 + dy) * 32 + (x0 + dx)];
            const float* kk = &ks[ci * 25];
            float v0 = 0.f, v1 = 0.f, v2 = 0.f, v3 = 0.f;
#pragma unroll
            for (int ky = 0; ky < 5; ky++) {
#pragma unroll
                for (int kx = 0; kx < 5; kx++) {
                    float wv = kk[ky * 5 + kx];
                    v0 += wv * patch[(ky)     * 6 + kx];
                    v1 += wv * patch[(ky)     * 6 + kx + 1];
                    v2 += wv * patch[(ky + 1) * 6 + kx];
                    v3 += wv * patch[(ky + 1) * 6 + kx + 1];
                }
            }
            float mx = fmaxf(fmaxf(v0, v1), fmaxf(v2, v3)) + b1[ci];
            outv = fmaxf(mx, 0.f);
        }
        outp[pos * P1STRIDE + ci] = to_tf32(outv);
    }
}

// ---------------------------------------------------------------------------
// Kernel 4: conv2 as implicit GEMM on mma.sync tf32.
// Per image: D(256x64) = sum over 25 taps of A_tap(256x32) x B_tap(32x64),
// where A_tap rows are in_lin rows shifted by ky*18+kx. 8 warps, warp tile
// 32x64 (2 m-tiles x 8 n-tiles). Weights double-buffered in 5-tap chunks.
// Epilogue: stage C -> smem, 2x2 pool + bias + relu, coalesced store.
// ---------------------------------------------------------------------------
#define C2M_THREADS 256
#define C2M_CHUNK_FL (5 * 2048)                      // 5 taps of packed B
#define C2M_SMEM_FL (P1FL + 2 * C2M_CHUNK_FL)        // 12096 + 20480 = 32576
#define C2M_STAG_STRIDE 66

__global__ __launch_bounds__(C2M_THREADS, 1) void conv2_mma_k(const float* __restrict__ b2) {
    extern __shared__ float sm[];
    float* in_lin = sm;                          // [336][36]
    float* bbuf0  = sm + P1FL;
    float* bbuf1  = bbuf0 + C2M_CHUNK_FL;

    int b = blockIdx.x;
    int t = threadIdx.x;
    int warp = t >> 5, lane = t & 31;
    int g = lane >> 2, tig = lane & 3;

    unsigned in_a = smem_u32(in_lin);
    unsigned b_a[2] = { smem_u32(bbuf0), smem_u32(bbuf1) };

    // group 0: input image + weight chunk 0
    {
        const char* ip = (const char*)(g_pool1 + (size_t)b * P1FL);
        for (int i = t; i < P1FL / 4; i += C2M_THREADS) cpa16(in_a + i * 16, ip + i * 16);
        const char* w0 = (const char*)g_K2p;
        for (int i = t; i < C2M_CHUNK_FL / 4; i += C2M_THREADS) cpa16(b_a[0] + i * 16, w0 + i * 16);
    }
    CP_COMMIT();
    // group 1: weight chunk 1
    {
        const char* w1 = (const char*)(g_K2p + C2M_CHUNK_FL);
        for (int i = t; i < C2M_CHUNK_FL / 4; i += C2M_THREADS) cpa16(b_a[1] + i * 16, w1 + i * 16);
    }
    CP_COMMIT();

    float c[16][4];
#pragma unroll
    for (int i = 0; i < 16; i++)
#pragma unroll
        for (int j = 0; j < 4; j++) c[i][j] = 0.f;

    for (int ch = 0; ch < 5; ch++) {           // ch == ky (5 taps per chunk)
        if (ch > 0) {
            __syncthreads();                   // prior chunk's buffer fully consumed
            if (ch + 1 < 5) {
                const char* wn = (const char*)(g_K2p + (ch + 1) * C2M_CHUNK_FL);
                unsigned dst = b_a[(ch + 1) & 1];
                for (int i = t; i < C2M_CHUNK_FL / 4; i += C2M_THREADS)
                    cpa16(dst + i * 16, wn + i * 16);
            }
            CP_COMMIT();
        }
        CP_WAIT1();
        __syncthreads();

        const float* bw = (ch & 1) ? bbuf1 : bbuf0;

#pragma unroll 1
        for (int t5 = 0; t5 < 5; t5++) {       // kx
            int shift = ch * 18 + t5;          // ky*18 + kx
            const float* bt = bw + t5 * 2048;
            const unsigned* au =
                (const unsigned*)(in_lin + (warp * 32 + g + shift) * P1STRIDE + tig);

#pragma unroll
            for (int ksI = 0; ksI < 4; ksI++) {
                int kb = ksI * 8;
                unsigned a00 = au[kb],                 a01 = au[8 * P1STRIDE + kb];
                unsigned a02 = au[kb + 4],             a03 = au[8 * P1STRIDE + kb + 4];
                unsigned a10 = au[16 * P1STRIDE + kb], a11 = au[24 * P1STRIDE + kb];
                unsigned a12 = au[16 * P1STRIDE + kb + 4], a13 = au[24 * P1STRIDE + kb + 4];

                const float* bks = bt + ksI * 512 + lane * 2;
#pragma unroll
                for (int nt = 0; nt < 8; nt++) {
                    float2 bv = *(const float2*)(bks + nt * 64);
                    unsigned b0 = __float_as_uint(bv.x);
                    unsigned b1 = __float_as_uint(bv.y);
                    mma8(c[nt],     a00, a01, a02, a03, b0, b1);
                    mma8(c[8 + nt], a10, a11, a12, a13, b0, b1);
                }
            }
        }
    }

    // ---- epilogue: stage C, pool 2x2, bias + relu, store ----
    __syncthreads();                           // everyone done reading bbuf
    float* stag = sm + P1FL;                   // [m(0..255)][co] stride 66

#pragma unroll
    for (int mt = 0; mt < 2; mt++) {
#pragma unroll
        for (int nt = 0; nt < 8; nt++) {
            float* s = stag + (warp * 32 + mt * 16 + g) * C2M_STAG_STRIDE + nt * 8 + 2 * tig;
            *(float2*)s = make_float2(c[mt * 8 + nt][0], c[mt * 8 + nt][1]);
            *(float2*)(s + 8 * C2M_STAG_STRIDE) = make_float2(c[mt * 8 + nt][2], c[mt * 8 + nt][3]);
        }
    }
    __syncthreads();

    for (int o = t; o < 3136; o += C2M_THREADS) {
        int pos = o >> 6, co = o & 63;
        int yp = pos / 7, xp = pos % 7;
        int m00 = yp * 36 + xp * 2;            // (2yp)*18 + 2xp
        float v0 = stag[m00 * C2M_STAG_STRIDE + co];
        float v1 = stag[(m00 + 1) * C2M_STAG_STRIDE + co];
        float v2 = stag[(m00 + 18) * C2M_STAG_STRIDE + co];
        float v3 = stag[(m00 + 19) * C2M_STAG_STRIDE + co];
        float mx = fmaxf(fmaxf(v0, v1), fmaxf(v2, v3)) + b2[co];
        g_pool2[(size_t)b * 3136 + pos * 64 + co] = fmaxf(mx, 0.f);
    }
}

// ---------------------------------------------------------------------------
// Kernel 5: fc1 GEMM  C[4096,128] = pool2[4096,3136] @ Wt[3136,128] + b, relu
// ---------------------------------------------------------------------------
__global__ __launch_bounds__(256) void fc1_k(const float* __restrict__ fc1_b) {
    __shared__ float As[32 * 32];
    __shared__ float Bs[32 * 128];

    int m0 = blockIdx.x * 32;
    int tid = threadIdx.x;
    int tm = tid / 32;
    int tn = tid % 32;

    float c[4][4];
#pragma unroll
    for (int i = 0; i < 4; i++)
#pragma unroll
        for (int j = 0; j < 4; j++) c[i][j] = 0.f;

    const float* A = g_pool2;

    for (int k0 = 0; k0 < 3136; k0 += 32) {
#pragma unroll
        for (int l = 0; l < 4; l++) {
            int i = tid + l * 256;
            int mm = i / 32, kk = i % 32;
            As[mm * 32 + kk] = A[(m0 + mm) * 3136 + k0 + kk];
        }
#pragma unroll
        for (int l = 0; l < 16; l++) {
            int i = tid + l * 256;
            int kk = i / 128, n = i % 128;
            Bs[kk * 128 + n] = g_fc1wt[(k0 + kk) * 128 + n];
        }
        __syncthreads();

#pragma unroll
        for (int kk = 0; kk < 32; kk++) {
            float a0 = As[(tm * 4 + 0) * 32 + kk];
            float a1 = As[(tm * 4 + 1) * 32 + kk];
            float a2 = As[(tm * 4 + 2) * 32 + kk];
            float a3 = As[(tm * 4 + 3) * 32 + kk];
            float4 bv = *(const float4*)&Bs[kk * 128 + tn * 4];
            c[0][0] += a0 * bv.x; c[0][1] += a0 * bv.y; c[0][2] += a0 * bv.z; c[0][3] += a0 * bv.w;
            c[1][0] += a1 * bv.x; c[1][1] += a1 * bv.y; c[1][2] += a1 * bv.z; c[1][3] += a1 * bv.w;
            c[2][0] += a2 * bv.x; c[2][1] += a2 * bv.y; c[2][2] += a2 * bv.z; c[2][3] += a2 * bv.w;
            c[3][0] += a3 * bv.x; c[3][1] += a3 * bv.y; c[3][2] += a3 * bv.z; c[3][3] += a3 * bv.w;
        }
        __syncthreads();
    }

#pragma unroll
    for (int j = 0; j < 4; j++) {
        int m = m0 + tm * 4 + j;
#pragma unroll
        for (int jj = 0; jj < 4; jj++) {
            int n = tn * 4 + jj;
            g_fc1o[m * 128 + n] = fmaxf(c[j][jj] + fc1_b[n], 0.f);
        }
    }
}

// ---------------------------------------------------------------------------
// Kernel 6: fc2  out[4096,10] = fc1o[4096,128] @ fc2_w[10,128]^T + b
// ---------------------------------------------------------------------------
__global__ __launch_bounds__(256) void fc2_k(const float* __restrict__ fc2_w,
                                             const float* __restrict__ fc2_b,
                                             float* __restrict__ out) {
    int idx = blockIdx.x * blockDim.x + threadIdx.x;
    if (idx >= NB * 10) return;
    int m = idx / 10, n = idx % 10;
    const float4* h = (const float4*)(g_fc1o + m * 128);
    const float4* w = (const float4*)(fc2_w + n * 128);
    float s = 0.f;
#pragma unroll
    for (int i = 0; i < 32; i++) {
        float4 a = h[i], bb = w[i];
        s += a.x * bb.x + a.y * bb.y + a.z * bb.z + a.w * bb.w;
    }
    out[idx] = s + fc2_b[n];
}

// ---------------------------------------------------------------------------
// Launch
// ---------------------------------------------------------------------------
extern "C" void kernel_launch(void* const* d_in, const int* in_sizes, int n_in,
                              void* d_out, int out_size) {
    const float* x     = (const float*)d_in[0];
    const float* w1    = (const float*)d_in[1];
    const float* p1    = (const float*)d_in[2];
    const float* b1    = (const float*)d_in[3];
    const float* w2    = (const float*)d_in[4];
    const float* p2    = (const float*)d_in[5];
    const float* b2    = (const float*)d_in[6];
    const float* fc1w  = (const float*)d_in[7];
    const float* fc1b  = (const float*)d_in[8];
    const float* fc2w  = (const float*)d_in[9];
    const float* fc2b  = (const float*)d_in[10];
    float* out = (float*)d_out;

    cudaFuncSetAttribute(conv2_mma_k, cudaFuncAttributeMaxDynamicSharedMemorySize,
                         C2M_SMEM_FL * 4);

    build_kernels_k<<<(32 + 64 * 32 + 127) / 128, 128>>>(w1, p1, w2, p2);
    repack_w2_k<<<(25 * 2048 + 255) / 256, 256>>>();
    transpose_fc1w_k<<<(3136 * 128 + 255) / 256, 256>>>(fc1w);
    conv1_k<<<NB, 256>>>(x, b1);
    conv2_mma_k<<<NB, C2M_THREADS, C2M_SMEM_FL * 4>>>(b2);
    fc1_k<<<NB / 32, 256>>>(fc1b);
    fc2_k<<<(NB * 10 + 255) / 256, 256>>>(fc2w, fc2b, out);
}

// round 10
// speedup vs baseline: 2.7584x; 1.1469x over previous
#include <cuda_runtime.h>
#include <math.h>

// ---------------------------------------------------------------------------
// Problem constants
// ---------------------------------------------------------------------------
#define NB     4096
// conv1: 1 -> 32 ch, 28x28, pad 2, pool -> 14x14
// conv2: 32 -> 64 ch, 14x14, pad 2, pool -> 7x7  (tensor-core implicit GEMM)
// fc1:   3136 -> 128, relu ; fc2: 128 -> 10

// conv1 output: padded spatial grid 18x18 (coords -2..15), channel-minor,
// position stride 36 floats (32 ci + 4 pad) -> conflict-free A fragments.
#define P1POS 324            // 18*18
#define P1POS_PAD 336        // pad so shifted A-fragment rows stay in-bounds
#define P1STRIDE 36
#define P1FL (P1POS_PAD * P1STRIDE)   // 12096 floats per image

// ---------------------------------------------------------------------------
// helpers
// ---------------------------------------------------------------------------
__device__ __forceinline__ unsigned smem_u32(const void* p) {
    unsigned a;
    asm("{ .reg .u64 t; cvta.to.shared.u64 t, %1; cvt.u32.u64 %0, t; }"
        : "=r"(a) : "l"(p));
    return a;
}
__device__ __forceinline__ void cpa16(unsigned s, const void* g) {
    asm volatile("cp.async.cg.shared.global [%0], [%1], 16;" :: "r"(s), "l"(g));
}
#define CP_COMMIT() asm volatile("cp.async.commit_group;")
#define CP_WAIT0()  asm volatile("cp.async.wait_group 0;" ::: "memory")

__device__ __forceinline__ float to_tf32(float x) {
    unsigned r;
    asm("cvt.rna.tf32.f32 %0, %1;" : "=r"(r) : "f"(x));
    return __uint_as_float(r);
}

__device__ __forceinline__ void mma8(float c[4],
                                     unsigned a0, unsigned a1, unsigned a2, unsigned a3,
                                     unsigned b0, unsigned b1) {
    asm volatile("mma.sync.aligned.m16n8k8.row.col.f32.tf32.tf32.f32 "
                 "{%0,%1,%2,%3}, {%4,%5,%6,%7}, {%8,%9}, {%0,%1,%2,%3};"
                 : "+f"(c[0]), "+f"(c[1]), "+f"(c[2]), "+f"(c[3])
                 : "r"(a0), "r"(a1), "r"(a2), "r"(a3), "r"(b0), "r"(b1));
}

// ---------------------------------------------------------------------------
// Device scratch
// ---------------------------------------------------------------------------
__device__ float g_K1[32 * 25];                  // [co][tap]
__device__ float g_K2[32 * 64 * 25];             // dense [ci][co][tap]
__device__ float g_K2p[25 * 2048];               // packed tf32 B frags [tap][ks][nt][lane][2]
__device__ float g_pool1[NB * P1FL];             // conv1 out, tf32-rounded, [pos][ci]
__device__ float g_pool2[NB * 64 * 7 * 7];       // [b][pos*64+co]
__device__ float g_fc1o[NB * 128];
__device__ float g_fc1wt[3136 * 128];            // permuted to match g_pool2 layout

// ---------------------------------------------------------------------------
// Kernel 1: build dense DCLS kernels
// ---------------------------------------------------------------------------
__global__ void build_kernels_k(const float* __restrict__ w1,
                                const float* __restrict__ p1,
                                const float* __restrict__ w2,
                                const float* __restrict__ p2) {
    int t = blockIdx.x * blockDim.x + threadIdx.x;
    if (t >= 32 + 64 * 32) return;

    float acc[36];
#pragma unroll
    for (int i = 0; i < 36; i++) acc[i] = 0.f;

    if (t < 32) {
        int co = t;
        for (int kc = 0; kc < 16; kc++) {
            float wv = w1[co * 16 + kc];
            float pa = p1[0 * 32 * 16 + co * 16 + kc];
            float pb = p1[1 * 32 * 16 + co * 16 + kc];
            pa = fminf(fmaxf(pa, -2.f), 2.f) + 2.f;
            pb = fminf(fmaxf(pb, -2.f), 2.f) + 2.f;
            int   i1 = (int)floorf(pa), i2 = (int)floorf(pb);
            float r1 = pa - (float)i1,  r2 = pb - (float)i2;
            acc[i1 * 6 + i2]           += wv * (1.f - r1) * (1.f - r2);
            acc[(i1 + 1) * 6 + i2]     += wv * r1 * (1.f - r2);
            acc[i1 * 6 + i2 + 1]       += wv * (1.f - r1) * r2;
            acc[(i1 + 1) * 6 + i2 + 1] += wv * r1 * r2;
        }
        for (int ky = 0; ky < 5; ky++)
            for (int kx = 0; kx < 5; kx++)
                g_K1[co * 25 + ky * 5 + kx] = acc[ky * 6 + kx];
    } else {
        int idx = t - 32;
        int co = idx / 32, ci = idx % 32;
        for (int kc = 0; kc < 32; kc++) {
            float wv = w2[(co * 32 + ci) * 32 + kc];
            float pa = p2[0 * 64 * 32 * 32 + (co * 32 + ci) * 32 + kc];
            float pb = p2[1 * 64 * 32 * 32 + (co * 32 + ci) * 32 + kc];
            pa = fminf(fmaxf(pa, -2.f), 2.f) + 2.f;
            pb = fminf(fmaxf(pb, -2.f), 2.f) + 2.f;
            int   i1 = (int)floorf(pa), i2 = (int)floorf(pb);
            float r1 = pa - (float)i1,  r2 = pb - (float)i2;
            acc[i1 * 6 + i2]           += wv * (1.f - r1) * (1.f - r2);
            acc[(i1 + 1) * 6 + i2]     += wv * r1 * (1.f - r2);
            acc[i1 * 6 + i2 + 1]       += wv * (1.f - r1) * r2;
            acc[(i1 + 1) * 6 + i2 + 1] += wv * r1 * r2;
        }
        for (int ky = 0; ky < 5; ky++)
            for (int kx = 0; kx < 5; kx++)
                g_K2[(ci * 64 + co) * 25 + ky * 5 + kx] = acc[ky * 6 + kx];
    }
}

// ---------------------------------------------------------------------------
// Kernel 1b: repack conv2 weights into per-fragment tf32 layout.
// packed idx = ((tap*4 + ks)*8 + nt)*64 + lane*2 + h
//   maps to B[k][n] with k = ks*8 + (lane&3) + 4h, n = nt*8 + (lane>>2)
// ---------------------------------------------------------------------------
__global__ void repack_w2_k() {
    int idx = blockIdx.x * 256 + threadIdx.x;
    if (idx >= 25 * 2048) return;
    int tap = idx / 2048, r = idx % 2048;
    int ks = r >> 9;
    int r2 = r & 511;
    int nt = r2 >> 6;
    int r3 = r2 & 63;
    int lane = r3 >> 1, h = r3 & 1;
    int k = ks * 8 + (lane & 3) + 4 * h;
    int n = nt * 8 + (lane >> 2);
    g_K2p[idx] = to_tf32(g_K2[(k * 64 + n) * 25 + tap]);
}

// ---------------------------------------------------------------------------
// Kernel 2: transpose+permute fc1_w to match g_pool2 [pos*64+co] k-order.
// ---------------------------------------------------------------------------
__global__ void transpose_fc1w_k(const float* __restrict__ w) {
    int idx = blockIdx.x * blockDim.x + threadIdx.x;
    if (idx < 3136 * 128) {
        int kp = idx / 128, n = idx % 128;
        int pos = kp >> 6, co = kp & 63;
        g_fc1wt[idx] = w[n * 3136 + co * 49 + pos];
    }
}

// ---------------------------------------------------------------------------
// Kernel 3: conv1 (1->32, pad 2) + bias + relu + 2x2 maxpool.
// ROW-STATIONARY: 448 threads = 14 pooled-rows x 32 co. Each thread computes
// two 28-wide conv rows in two column-halves with a 6-row rolling window:
// ~1400 FMA vs ~320 broadcast LDS per thread, no div/mod in the hot loop.
// Warp = one pooled row, lanes = co -> coalesced [pos][ci] stores.
// ---------------------------------------------------------------------------
#define C1_THREADS 448

__global__ __launch_bounds__(C1_THREADS, 2) void conv1_k(const float* __restrict__ x,
                                                         const float* __restrict__ b1) {
    __shared__ float xs[32 * 32];   // rows/cols -2..29 (zero-padded)
    __shared__ float ks[800];       // 32 x 25
    int b = blockIdx.x;
    int t = threadIdx.x;
    const float* xp = x + b * 784;
    for (int i = t; i < 1024; i += C1_THREADS) {
        int r = (i >> 5) - 2, c = (i & 31) - 2;
        xs[i] = (r >= 0 && r < 28 && c >= 0 && c < 28) ? xp[r * 28 + c] : 0.f;
    }
    for (int i = t; i < 800; i += C1_THREADS) ks[i] = g_K1[i];

    float* outp = g_pool1 + (size_t)b * P1FL;
    // zero border cells: rows pr {0,1,16,17} (72 pos), cols pc {0,1,16,17}
    // for pr 2..15 (56 pos), tail pad rows 324..335 (12 pos) -> 140 pos x 32 ci
    for (int i = t; i < 140 * 32; i += C1_THREADS) {
        int p = i >> 5, ci = i & 31;
        int pos;
        if (p < 72) {
            int r = p / 18;
            int pr = (r < 2) ? r : 14 + r;
            pos = pr * 18 + (p - r * 18);
        } else if (p < 128) {
            int q = p - 72;
            int pr = 2 + (q >> 2);
            int c4 = q & 3;
            int pc = (c4 < 2) ? c4 : 14 + c4;
            pos = pr * 18 + pc;
        } else {
            pos = 324 + (p - 128);
        }
        outp[pos * P1STRIDE + ci] = 0.f;
    }
    __syncthreads();

    int co = t & 31;     // lane
    int yp = t >> 5;     // pooled row 0..13
    const float* wp = ks + co * 25;
    float bias = b1[co];

#pragma unroll 1
    for (int half = 0; half < 2; half++) {
        int x0 = half * 14;                  // conv-col base
        float acc0[14], acc1[14];
#pragma unroll
        for (int i = 0; i < 14; i++) { acc0[i] = 0.f; acc1[i] = 0.f; }

#pragma unroll
        for (int j = 0; j < 6; j++) {
            float row[18];
            const float* rp = xs + (2 * yp + j) * 32 + x0;
#pragma unroll
            for (int c = 0; c < 18; c++) row[c] = rp[c];   // broadcast LDS

            if (j < 5) {                     // conv row 2yp, ky = j
#pragma unroll
                for (int kx = 0; kx < 5; kx++) {
                    float wv = wp[j * 5 + kx];
#pragma unroll
                    for (int xx = 0; xx < 14; xx++)
                        acc0[xx] += wv * row[xx + kx];
                }
            }
            if (j >= 1) {                    // conv row 2yp+1, ky = j-1
#pragma unroll
                for (int kx = 0; kx < 5; kx++) {
                    float wv = wp[(j - 1) * 5 + kx];
#pragma unroll
                    for (int xx = 0; xx < 14; xx++)
                        acc1[xx] += wv * row[xx + kx];
                }
            }
        }

#pragma unroll
        for (int p_ = 0; p_ < 7; p_++) {
            float m = fmaxf(fmaxf(acc0[2 * p_], acc0[2 * p_ + 1]),
                            fmaxf(acc1[2 * p_], acc1[2 * p_ + 1]));
            int xq = half * 7 + p_;
            int pos = (yp + 2) * 18 + (xq + 2);
            outp[pos * P1STRIDE + co] = to_tf32(fmaxf(m + bias, 0.f));
        }
    }
}

// ---------------------------------------------------------------------------
// Kernel 4: conv2 as implicit GEMM on mma.sync tf32.
// Per image: D(256x64) = sum over 25 taps of A_tap(256x32) x B_tap(32x64).
// SINGLE weight buffer (chunk-serial cp.async) + C-staging overlaid onto the
// dead input buffer -> smem 89.3 KB -> 2 CTAs/SM hide each other's gaps.
// ---------------------------------------------------------------------------
#define C2M_THREADS 256
#define C2M_CHUNK_FL (5 * 2048)                      // 5 taps of packed B
#define C2M_SMEM_FL (P1FL + C2M_CHUNK_FL)            // 12096 + 10240 = 22336
#define C2M_STAG_STRIDE 66                           // staging 256*66 = 16896 <= 22336

__global__ __launch_bounds__(C2M_THREADS, 2) void conv2_mma_k(const float* __restrict__ b2) {
    extern __shared__ float sm[];
    float* in_lin = sm;                          // [336][36]
    float* bbuf   = sm + P1FL;                   // single 5-tap weight chunk

    int b = blockIdx.x;
    int t = threadIdx.x;
    int warp = t >> 5, lane = t & 31;
    int g = lane >> 2, tig = lane & 3;

    unsigned in_a = smem_u32(in_lin);
    unsigned b_a  = smem_u32(bbuf);

    // group 0: input image + weight chunk 0
    {
        const char* ip = (const char*)(g_pool1 + (size_t)b * P1FL);
        for (int i = t; i < P1FL / 4; i += C2M_THREADS) cpa16(in_a + i * 16, ip + i * 16);
        const char* w0 = (const char*)g_K2p;
        for (int i = t; i < C2M_CHUNK_FL / 4; i += C2M_THREADS) cpa16(b_a + i * 16, w0 + i * 16);
    }
    CP_COMMIT();

    float c[16][4];
#pragma unroll
    for (int i = 0; i < 16; i++)
#pragma unroll
        for (int j = 0; j < 4; j++) c[i][j] = 0.f;

    for (int ch = 0; ch < 5; ch++) {           // ch == ky (5 taps per chunk)
        CP_WAIT0();
        __syncthreads();

#pragma unroll 1
        for (int t5 = 0; t5 < 5; t5++) {       // kx
            int shift = ch * 18 + t5;          // ky*18 + kx
            const float* bt = bbuf + t5 * 2048;
            const unsigned* au =
                (const unsigned*)(in_lin + (warp * 32 + g + shift) * P1STRIDE + tig);

#pragma unroll
            for (int ksI = 0; ksI < 4; ksI++) {
                int kb = ksI * 8;
                unsigned a00 = au[kb],                 a01 = au[8 * P1STRIDE + kb];
                unsigned a02 = au[kb + 4],             a03 = au[8 * P1STRIDE + kb + 4];
                unsigned a10 = au[16 * P1STRIDE + kb], a11 = au[24 * P1STRIDE + kb];
                unsigned a12 = au[16 * P1STRIDE + kb + 4], a13 = au[24 * P1STRIDE + kb + 4];

                const float* bks = bt + ksI * 512 + lane * 2;
#pragma unroll
                for (int nt = 0; nt < 8; nt++) {
                    float2 bv = *(const float2*)(bks + nt * 64);
                    unsigned b0 = __float_as_uint(bv.x);
                    unsigned b1 = __float_as_uint(bv.y);
                    mma8(c[nt],     a00, a01, a02, a03, b0, b1);
                    mma8(c[8 + nt], a10, a11, a12, a13, b0, b1);
                }
            }
        }
        __syncthreads();                       // chunk consumed
        if (ch + 1 < 5) {
            const char* wn = (const char*)(g_K2p + (ch + 1) * C2M_CHUNK_FL);
            for (int i = t; i < C2M_CHUNK_FL / 4; i += C2M_THREADS)
                cpa16(b_a + i * 16, wn + i * 16);
            CP_COMMIT();
        }
    }

    // ---- epilogue: stage C over the dead input buffer, pool, store ----
    float* stag = sm;                          // [m(0..255)][co] stride 66

#pragma unroll
    for (int mt = 0; mt < 2; mt++) {
#pragma unroll
        for (int nt = 0; nt < 8; nt++) {
            float* s = stag + (warp * 32 + mt * 16 + g) * C2M_STAG_STRIDE + nt * 8 + 2 * tig;
            *(float2*)s = make_float2(c[mt * 8 + nt][0], c[mt * 8 + nt][1]);
            *(float2*)(s + 8 * C2M_STAG_STRIDE) = make_float2(c[mt * 8 + nt][2], c[mt * 8 + nt][3]);
        }
    }
    __syncthreads();

    for (int o = t; o < 3136; o += C2M_THREADS) {
        int pos = o >> 6, co = o & 63;
        int yp = pos / 7, xp = pos % 7;
        int m00 = yp * 36 + xp * 2;            // (2yp)*18 + 2xp
        float v0 = stag[m00 * C2M_STAG_STRIDE + co];
        float v1 = stag[(m00 + 1) * C2M_STAG_STRIDE + co];
        float v2 = stag[(m00 + 18) * C2M_STAG_STRIDE + co];
        float v3 = stag[(m00 + 19) * C2M_STAG_STRIDE + co];
        float mx = fmaxf(fmaxf(v0, v1), fmaxf(v2, v3)) + b2[co];
        g_pool2[(size_t)b * 3136 + pos * 64 + co] = fmaxf(mx, 0.f);
    }
}

// ---------------------------------------------------------------------------
// Kernel 5: fc1 GEMM  C[4096,128] = pool2[4096,3136] @ Wt[3136,128] + b, relu
// ---------------------------------------------------------------------------
__global__ __launch_bounds__(256) void fc1_k(const float* __restrict__ fc1_b) {
    __shared__ float As[32 * 32];
    __shared__ float Bs[32 * 128];

    int m0 = blockIdx.x * 32;
    int tid = threadIdx.x;
    int tm = tid / 32;
    int tn = tid % 32;

    float c[4][4];
#pragma unroll
    for (int i = 0; i < 4; i++)
#pragma unroll
        for (int j = 0; j < 4; j++) c[i][j] = 0.f;

    const float* A = g_pool2;

    for (int k0 = 0; k0 < 3136; k0 += 32) {
#pragma unroll
        for (int l = 0; l < 4; l++) {
            int i = tid + l * 256;
            int mm = i / 32, kk = i % 32;
            As[mm * 32 + kk] = A[(m0 + mm) * 3136 + k0 + kk];
        }
#pragma unroll
        for (int l = 0; l < 16; l++) {
            int i = tid + l * 256;
            int kk = i / 128, n = i % 128;
            Bs[kk * 128 + n] = g_fc1wt[(k0 + kk) * 128 + n];
        }
        __syncthreads();

#pragma unroll
        for (int kk = 0; kk < 32; kk++) {
            float a0 = As[(tm * 4 + 0) * 32 + kk];
            float a1 = As[(tm * 4 + 1) * 32 + kk];
            float a2 = As[(tm * 4 + 2) * 32 + kk];
            float a3 = As[(tm * 4 + 3) * 32 + kk];
            float4 bv = *(const float4*)&Bs[kk * 128 + tn * 4];
            c[0][0] += a0 * bv.x; c[0][1] += a0 * bv.y; c[0][2] += a0 * bv.z; c[0][3] += a0 * bv.w;
            c[1][0] += a1 * bv.x; c[1][1] += a1 * bv.y; c[1][2] += a1 * bv.z; c[1][3] += a1 * bv.w;
            c[2][0] += a2 * bv.x; c[2][1] += a2 * bv.y; c[2][2] += a2 * bv.z; c[2][3] += a2 * bv.w;
            c[3][0] += a3 * bv.x; c[3][1] += a3 * bv.y; c[3][2] += a3 * bv.z; c[3][3] += a3 * bv.w;
        }
        __syncthreads();
    }

#pragma unroll
    for (int j = 0; j < 4; j++) {
        int m = m0 + tm * 4 + j;
#pragma unroll
        for (int jj = 0; jj < 4; jj++) {
            int n = tn * 4 + jj;
            g_fc1o[m * 128 + n] = fmaxf(c[j][jj] + fc1_b[n], 0.f);
        }
    }
}

// ---------------------------------------------------------------------------
// Kernel 6: fc2  out[4096,10] = fc1o[4096,128] @ fc2_w[10,128]^T + b
// ---------------------------------------------------------------------------
__global__ __launch_bounds__(256) void fc2_k(const float* __restrict__ fc2_w,
                                             const float* __restrict__ fc2_b,
                                             float* __restrict__ out) {
    int idx = blockIdx.x * blockDim.x + threadIdx.x;
    if (idx >= NB * 10) return;
    int m = idx / 10, n = idx % 10;
    const float4* h = (const float4*)(g_fc1o + m * 128);
    const float4* w = (const float4*)(fc2_w + n * 128);
    float s = 0.f;
#pragma unroll
    for (int i = 0; i < 32; i++) {
        float4 a = h[i], bb = w[i];
        s += a.x * bb.x + a.y * bb.y + a.z * bb.z + a.w * bb.w;
    }
    out[idx] = s + fc2_b[n];
}

// ---------------------------------------------------------------------------
// Launch
// ---------------------------------------------------------------------------
extern "C" void kernel_launch(void* const* d_in, const int* in_sizes, int n_in,
                              void* d_out, int out_size) {
    const float* x     = (const float*)d_in[0];
    const float* w1    = (const float*)d_in[1];
    const float* p1    = (const float*)d_in[2];
    const float* b1    = (const float*)d_in[3];
    const float* w2    = (const float*)d_in[4];
    const float* p2    = (const float*)d_in[5];
    const float* b2    = (const float*)d_in[6];
    const float* fc1w  = (const float*)d_in[7];
    const float* fc1b  = (const float*)d_in[8];
    const float* fc2w  = (const float*)d_in[9];
    const float* fc2b  = (const float*)d_in[10];
    float* out = (float*)d_out;

    cudaFuncSetAttribute(conv2_mma_k, cudaFuncAttributeMaxDynamicSharedMemorySize,
                         C2M_SMEM_FL * 4);

    build_kernels_k<<<(32 + 64 * 32 + 127) / 128, 128>>>(w1, p1, w2, p2);
    repack_w2_k<<<(25 * 2048 + 255) / 256, 256>>>();
    transpose_fc1w_k<<<(3136 * 128 + 255) / 256, 256>>>(fc1w);
    conv1_k<<<NB, C1_THREADS>>>(x, b1);
    conv2_mma_k<<<NB, C2M_THREADS, C2M_SMEM_FL * 4>>>(b2);
    fc1_k<<<NB / 32, 256>>>(fc1b);
    fc2_k<<<(NB * 10 + 255) / 256, 256>>>(fc2w, fc2b, out);
}